// round 7
// baseline (speedup 1.0000x reference)
#include <cuda_runtime.h>
#include <cstdint>

// ---------------- problem constants ----------------
constexpr int B    = 4;
constexpr int SEQ  = 4096;
constexpr int DIM  = 512;
constexpr int H    = 8;
constexpr int DH   = 64;     // DIM / H
constexpr int LM   = 256;    // landmarks
constexpr int LSZ  = 16;     // SEQ / LM
constexpr int BH   = B * H;  // 32
constexpr int CK   = 33;     // conv kernel
constexpr int TOK  = B * SEQ;        // 16384
constexpr int QKVW = 3 * DIM;        // 1536

// ---------------- scratch (static device memory; no allocations) ----------------
__device__ float g_xn  [TOK * DIM];
__device__ float g_qkv [(long)TOK * QKVW];
__device__ float g_ql  [BH * LM * DH];
__device__ float g_kl  [BH * LM * DH];
__device__ float g_a2  [BH * LM * LM];
__device__ float g_z   [BH * LM * LM];
__device__ float g_z2  [BH * LM * LM];
__device__ float g_xz  [BH * LM * LM];
__device__ float g_t   [BH * LM * LM];
__device__ float g_w   [BH * LM * LM];
__device__ float g_a3v [BH * LM * DH];
__device__ float g_za3v[BH * LM * DH];
__device__ float g_res [(long)BH * SEQ * DH];
__device__ float g_ctx [TOK * DIM];
__device__ int   g_rowmax_i;
__device__ int   g_colmax_i;

// ---------------- tf32 helpers ----------------
__device__ __forceinline__ uint32_t f2tf(float f) {
    uint32_t u;
    asm("cvt.rna.tf32.f32 %0, %1;" : "=r"(u) : "f"(f));
    return u;
}

__device__ __forceinline__ void mma_tf32(float* c, const uint32_t* a, const uint32_t* b) {
    asm volatile(
        "mma.sync.aligned.m16n8k8.row.col.f32.tf32.tf32.f32 "
        "{%0,%1,%2,%3}, {%4,%5,%6,%7}, {%8,%9}, {%0,%1,%2,%3};"
        : "+f"(c[0]), "+f"(c[1]), "+f"(c[2]), "+f"(c[3])
        : "r"(a[0]), "r"(a[1]), "r"(a[2]), "r"(a[3]), "r"(b[0]), "r"(b[1]));
}

// ---------------- batched tf32 tensor-core GEMM ----------------
template<int BM, int BN, int BK, int WM, int WN, bool TB>
__global__ __launch_bounds__(32 * WM * WN, 2)
void tgemm(const float* __restrict__ A, const float* __restrict__ Bm, float* __restrict__ C,
           int lda, int ldb, int ldc, int Kn,
           long sA1, long sA2, long sB1, long sB2, long sC1, long sC2,
           float alpha, const float* __restrict__ bias,
           const float* __restrict__ resid, float rscale, int ldr, long sR1, long sR2)
{
    constexpr int NT  = 32 * WM * WN;
    constexpr int SA  = BK + 4;
    constexpr int SB  = TB ? (BK + 4) : (BN + 8);
    constexpr int MT  = BM / WM / 16;
    constexpr int NTl = BN / WN / 8;
    constexpr int LA  = BM * BK / (4 * NT);
    constexpr int LB  = BN * BK / (4 * NT);

    const int zb = blockIdx.z / H;
    const int zh = blockIdx.z % H;
    A  += zb * sA1 + zh * sA2;
    Bm += zb * sB1 + zh * sB2;
    C  += zb * sC1 + zh * sC2;
    if (resid) resid += zb * sR1 + zh * sR2;

    __shared__ __align__(16) uint32_t As[BM * SA];
    __shared__ __align__(16) uint32_t Bs[(TB ? BN : BK) * SB];

    const int tid  = threadIdx.x;
    const int lane = tid & 31;
    const int warp = tid >> 5;
    const int wm   = warp / WN;
    const int wn   = warp % WN;
    const int m_woff = wm * (BM / WM);
    const int n_woff = wn * (BN / WN);
    const int row0 = blockIdx.y * BM;
    const int col0 = blockIdx.x * BN;
    const int g4   = lane >> 2;
    const int t4   = lane & 3;

    int rA[LA], cA[LA];
#pragma unroll
    for (int i = 0; i < LA; i++) {
        const int idx = tid + i * NT;
        rA[i] = idx / (BK / 4);
        cA[i] = (idx % (BK / 4)) * 4;
    }
    int rB[LB], cB[LB];
#pragma unroll
    for (int i = 0; i < LB; i++) {
        const int idx = tid + i * NT;
        if (TB) { rB[i] = idx / (BK / 4); cB[i] = (idx % (BK / 4)) * 4; }
        else    { rB[i] = idx / (BN / 4); cB[i] = (idx % (BN / 4)) * 4; }
    }

    float4 pa[LA], pb[LB];
    auto loadG = [&](int k0) {
#pragma unroll
        for (int i = 0; i < LA; i++)
            pa[i] = *reinterpret_cast<const float4*>(A + (long)(row0 + rA[i]) * lda + k0 + cA[i]);
#pragma unroll
        for (int i = 0; i < LB; i++) {
            if (TB) pb[i] = *reinterpret_cast<const float4*>(Bm + (long)(col0 + rB[i]) * ldb + k0 + cB[i]);
            else    pb[i] = *reinterpret_cast<const float4*>(Bm + (long)(k0 + rB[i]) * ldb + col0 + cB[i]);
        }
    };
    auto storeS = [&]() {
#pragma unroll
        for (int i = 0; i < LA; i++) {
            uint4 t = { f2tf(pa[i].x), f2tf(pa[i].y), f2tf(pa[i].z), f2tf(pa[i].w) };
            *reinterpret_cast<uint4*>(&As[rA[i] * SA + cA[i]]) = t;
        }
#pragma unroll
        for (int i = 0; i < LB; i++) {
            uint4 t = { f2tf(pb[i].x), f2tf(pb[i].y), f2tf(pb[i].z), f2tf(pb[i].w) };
            *reinterpret_cast<uint4*>(&Bs[rB[i] * SB + cB[i]]) = t;
        }
    };

    float acc[MT][NTl][4];
#pragma unroll
    for (int i = 0; i < MT; i++)
#pragma unroll
        for (int j = 0; j < NTl; j++)
#pragma unroll
            for (int q = 0; q < 4; q++) acc[i][j][q] = 0.f;

    loadG(0);
    for (int k0 = 0; k0 < Kn; k0 += BK) {
        storeS();
        __syncthreads();
        if (k0 + BK < Kn) loadG(k0 + BK);
#pragma unroll
        for (int kb = 0; kb < BK; kb += 8) {
            uint32_t af[MT][4];
#pragma unroll
            for (int mt = 0; mt < MT; mt++) {
                const int rm = m_woff + mt * 16 + g4;
                const int kc = kb + t4;
                af[mt][0] = As[rm * SA + kc];
                af[mt][1] = As[(rm + 8) * SA + kc];
                af[mt][2] = As[rm * SA + kc + 4];
                af[mt][3] = As[(rm + 8) * SA + kc + 4];
            }
#pragma unroll
            for (int nt = 0; nt < NTl; nt++) {
                const int cn = n_woff + nt * 8 + g4;
                uint32_t bf[2];
                if (TB) {
                    bf[0] = Bs[cn * SB + kb + t4];
                    bf[1] = Bs[cn * SB + kb + t4 + 4];
                } else {
                    bf[0] = Bs[(kb + t4) * SB + cn];
                    bf[1] = Bs[(kb + t4 + 4) * SB + cn];
                }
#pragma unroll
                for (int mt = 0; mt < MT; mt++)
                    mma_tf32(acc[mt][nt], af[mt], bf);
            }
        }
        __syncthreads();
    }

#pragma unroll
    for (int mt = 0; mt < MT; mt++) {
        const int r = row0 + m_woff + mt * 16 + g4;
#pragma unroll
        for (int nt = 0; nt < NTl; nt++) {
            const int c = col0 + n_woff + nt * 8 + 2 * t4;
            float v0 = alpha * acc[mt][nt][0];
            float v1 = alpha * acc[mt][nt][1];
            float v2 = alpha * acc[mt][nt][2];
            float v3 = alpha * acc[mt][nt][3];
            if (bias) { v0 += bias[c]; v1 += bias[c + 1]; v2 += bias[c]; v3 += bias[c + 1]; }
            if (resid) {
                const float2 r0 = *reinterpret_cast<const float2*>(resid + (long)r * ldr + c);
                const float2 r1 = *reinterpret_cast<const float2*>(resid + (long)(r + 8) * ldr + c);
                v0 += rscale * r0.x; v1 += rscale * r0.y;
                v2 += rscale * r1.x; v3 += rscale * r1.y;
            }
            *reinterpret_cast<float2*>(C + (long)r * ldc + c)       = make_float2(v0, v1);
            *reinterpret_cast<float2*>(C + (long)(r + 8) * ldc + c) = make_float2(v2, v3);
        }
    }
}

// ---------------- GEMM vs kl^T with fused full-row softmax (N=256/CTA) ----------
// C[z] = softmax_row(alpha * A[z] @ kl[z]^T). BM=128, 512 threads.
// Used for a2 = softmax(ql @ kl^T).
__global__ __launch_bounds__(512, 1)
void tgemm_sm(const float* __restrict__ Abase, int lda, long sA,
              const float* __restrict__ kl, float* __restrict__ Cbase, long sC,
              float alpha)
{
    constexpr int SA = 20, SB = 20;
    const float* A  = Abase + (long)blockIdx.z * sA;
    const float* Bp = kl + (long)blockIdx.z * LM * DH;
    float* Cp = Cbase + (long)blockIdx.z * sC;

    __shared__ __align__(16) uint32_t As[128 * SA];
    __shared__ __align__(16) uint32_t Bs[256 * SB];
    __shared__ float red[128][4];

    const int tid = threadIdx.x, lane = tid & 31, warp = tid >> 5;
    const int wm = warp >> 2, wn = warp & 3;
    const int m_woff = wm * 32, n_woff = wn * 64;
    const int row0 = blockIdx.y * 128;
    const int g4 = lane >> 2, t4 = lane & 3;

    const int rA = tid >> 2, cA = (tid & 3) << 2;
    const int rB0 = tid >> 2, rB1 = (tid + 512) >> 2;

    float4 pa, pb0, pb1;
    auto loadG = [&](int k0) {
        pa  = *reinterpret_cast<const float4*>(A + (long)(row0 + rA) * lda + k0 + cA);
        pb0 = *reinterpret_cast<const float4*>(Bp + (long)rB0 * DH + k0 + cA);
        pb1 = *reinterpret_cast<const float4*>(Bp + (long)rB1 * DH + k0 + cA);
    };
    auto storeS = [&]() {
        uint4 ta = { f2tf(pa.x), f2tf(pa.y), f2tf(pa.z), f2tf(pa.w) };
        *reinterpret_cast<uint4*>(&As[rA * SA + cA]) = ta;
        uint4 t0 = { f2tf(pb0.x), f2tf(pb0.y), f2tf(pb0.z), f2tf(pb0.w) };
        *reinterpret_cast<uint4*>(&Bs[rB0 * SB + cA]) = t0;
        uint4 t1 = { f2tf(pb1.x), f2tf(pb1.y), f2tf(pb1.z), f2tf(pb1.w) };
        *reinterpret_cast<uint4*>(&Bs[rB1 * SB + cA]) = t1;
    };

    float acc[2][8][4];
#pragma unroll
    for (int i = 0; i < 2; i++)
#pragma unroll
        for (int j = 0; j < 8; j++)
#pragma unroll
            for (int q = 0; q < 4; q++) acc[i][j][q] = 0.f;

    loadG(0);
    for (int k0 = 0; k0 < DH; k0 += 16) {
        storeS();
        __syncthreads();
        if (k0 + 16 < DH) loadG(k0 + 16);
#pragma unroll
        for (int kb = 0; kb < 16; kb += 8) {
            uint32_t af[2][4];
#pragma unroll
            for (int mt = 0; mt < 2; mt++) {
                const int rm = m_woff + mt * 16 + g4;
                const int kc = kb + t4;
                af[mt][0] = As[rm * SA + kc];
                af[mt][1] = As[(rm + 8) * SA + kc];
                af[mt][2] = As[rm * SA + kc + 4];
                af[mt][3] = As[(rm + 8) * SA + kc + 4];
            }
#pragma unroll
            for (int nt = 0; nt < 8; nt++) {
                const int cn = n_woff + nt * 8 + g4;
                uint32_t bf[2] = { Bs[cn * SB + kb + t4], Bs[cn * SB + kb + t4 + 4] };
#pragma unroll
                for (int mt = 0; mt < 2; mt++) mma_tf32(acc[mt][nt], af[mt], bf);
            }
        }
        __syncthreads();
    }

#pragma unroll
    for (int mt = 0; mt < 2; mt++)
#pragma unroll
        for (int nt = 0; nt < 8; nt++)
#pragma unroll
            for (int q = 0; q < 4; q++) acc[mt][nt][q] *= alpha;

    float lmax[2][2] = { {-1e30f, -1e30f}, {-1e30f, -1e30f} };
#pragma unroll
    for (int mt = 0; mt < 2; mt++)
#pragma unroll
        for (int nt = 0; nt < 8; nt++)
#pragma unroll
            for (int q = 0; q < 4; q++)
                lmax[mt][q >> 1] = fmaxf(lmax[mt][q >> 1], acc[mt][nt][q]);
#pragma unroll
    for (int o = 1; o <= 2; o <<= 1)
#pragma unroll
        for (int mt = 0; mt < 2; mt++)
#pragma unroll
            for (int hh = 0; hh < 2; hh++)
                lmax[mt][hh] = fmaxf(lmax[mt][hh], __shfl_xor_sync(0xffffffffu, lmax[mt][hh], o));
    if (t4 == 0)
#pragma unroll
        for (int mt = 0; mt < 2; mt++)
#pragma unroll
            for (int hh = 0; hh < 2; hh++)
                red[m_woff + mt * 16 + hh * 8 + g4][wn] = lmax[mt][hh];
    __syncthreads();
    float rmax[2][2];
#pragma unroll
    for (int mt = 0; mt < 2; mt++)
#pragma unroll
        for (int hh = 0; hh < 2; hh++) {
            const int rb = m_woff + mt * 16 + hh * 8 + g4;
            rmax[mt][hh] = fmaxf(fmaxf(red[rb][0], red[rb][1]), fmaxf(red[rb][2], red[rb][3]));
        }
    __syncthreads();
    float lsum[2][2] = { {0.f, 0.f}, {0.f, 0.f} };
#pragma unroll
    for (int mt = 0; mt < 2; mt++)
#pragma unroll
        for (int nt = 0; nt < 8; nt++)
#pragma unroll
            for (int q = 0; q < 4; q++) {
                const float e = expf(acc[mt][nt][q] - rmax[mt][q >> 1]);
                acc[mt][nt][q] = e;
                lsum[mt][q >> 1] += e;
            }
#pragma unroll
    for (int o = 1; o <= 2; o <<= 1)
#pragma unroll
        for (int mt = 0; mt < 2; mt++)
#pragma unroll
            for (int hh = 0; hh < 2; hh++)
                lsum[mt][hh] += __shfl_xor_sync(0xffffffffu, lsum[mt][hh], o);
    if (t4 == 0)
#pragma unroll
        for (int mt = 0; mt < 2; mt++)
#pragma unroll
            for (int hh = 0; hh < 2; hh++)
                red[m_woff + mt * 16 + hh * 8 + g4][wn] = lsum[mt][hh];
    __syncthreads();
    float rinv[2][2];
#pragma unroll
    for (int mt = 0; mt < 2; mt++)
#pragma unroll
        for (int hh = 0; hh < 2; hh++) {
            const int rb = m_woff + mt * 16 + hh * 8 + g4;
            rinv[mt][hh] = 1.0f / (red[rb][0] + red[rb][1] + red[rb][2] + red[rb][3]);
        }
#pragma unroll
    for (int mt = 0; mt < 2; mt++) {
        const int r = row0 + m_woff + mt * 16 + g4;
#pragma unroll
        for (int nt = 0; nt < 8; nt++) {
            const int c = n_woff + nt * 8 + 2 * t4;
            *reinterpret_cast<float2*>(Cp + (long)r * LM + c) =
                make_float2(acc[mt][nt][0] * rinv[mt][0], acc[mt][nt][1] * rinv[mt][0]);
            *reinterpret_cast<float2*>(Cp + (long)(r + 8) * LM + c) =
                make_float2(acc[mt][nt][2] * rinv[mt][1], acc[mt][nt][3] * rinv[mt][1]);
        }
    }
}

// ---------------- fused a1 consumer: ctx = softmax(0.125 q@kl^T) @ za3v + res ---
// Grid (SEQ/128, BH), 512 threads. a1 is never materialized.
constexpr int FA_PS_OFF  = 8704;   // Zs offset (words)
constexpr int FA_RED_OFF = 13312;  // red offset (words)
constexpr int FA_SMEM_WORDS = 13824;

__global__ __launch_bounds__(512, 1)
void fused_a1ctx(const float* __restrict__ qkv, const float* __restrict__ kl,
                 const float* __restrict__ za3v, const float* __restrict__ res,
                 float* __restrict__ ctx)
{
    constexpr int SA = 20, SB = 20;
    extern __shared__ uint32_t dsm[];
    uint32_t* As = dsm;                 // [128][20] phase 1
    uint32_t* Bs = dsm + 2560;          // [256][20] phase 1
    uint32_t* Ps = dsm;                 // [128][68] phase 2 (aliases As/Bs)
    uint32_t* Zs = dsm + FA_PS_OFF;     // [64][72]  phase 2
    float*    red = (float*)(dsm + FA_RED_OFF);  // [128][4]

    const int bh = blockIdx.y;
    const int zb = bh >> 3, zh = bh & 7;
    const float* A  = qkv + (long)zb * SEQ * QKVW + (long)zh * DH;
    const float* Bp = kl + (long)bh * LM * DH;

    const int tid = threadIdx.x, lane = tid & 31, warp = tid >> 5;
    const int wm = warp >> 2, wn = warp & 3;
    const int m_woff = wm * 32, n_woff = wn * 64;
    const int row0 = blockIdx.x * 128;
    const int g4 = lane >> 2, t4 = lane & 3;

    const int rA = tid >> 2, cA = (tid & 3) << 2;
    const int rB0 = tid >> 2, rB1 = (tid + 512) >> 2;

    float4 pa, pb0, pb1;
    auto loadG = [&](int k0) {
        pa  = *reinterpret_cast<const float4*>(A + (long)(row0 + rA) * QKVW + k0 + cA);
        pb0 = *reinterpret_cast<const float4*>(Bp + (long)rB0 * DH + k0 + cA);
        pb1 = *reinterpret_cast<const float4*>(Bp + (long)rB1 * DH + k0 + cA);
    };
    auto storeS = [&]() {
        uint4 ta = { f2tf(pa.x), f2tf(pa.y), f2tf(pa.z), f2tf(pa.w) };
        *reinterpret_cast<uint4*>(&As[rA * SA + cA]) = ta;
        uint4 t0 = { f2tf(pb0.x), f2tf(pb0.y), f2tf(pb0.z), f2tf(pb0.w) };
        *reinterpret_cast<uint4*>(&Bs[rB0 * SB + cA]) = t0;
        uint4 t1 = { f2tf(pb1.x), f2tf(pb1.y), f2tf(pb1.z), f2tf(pb1.w) };
        *reinterpret_cast<uint4*>(&Bs[rB1 * SB + cA]) = t1;
    };

    float acc[2][8][4];
#pragma unroll
    for (int i = 0; i < 2; i++)
#pragma unroll
        for (int j = 0; j < 8; j++)
#pragma unroll
            for (int q = 0; q < 4; q++) acc[i][j][q] = 0.f;

    loadG(0);
    for (int k0 = 0; k0 < DH; k0 += 16) {
        storeS();
        __syncthreads();
        if (k0 + 16 < DH) loadG(k0 + 16);
#pragma unroll
        for (int kb = 0; kb < 16; kb += 8) {
            uint32_t af[2][4];
#pragma unroll
            for (int mt = 0; mt < 2; mt++) {
                const int rm = m_woff + mt * 16 + g4;
                const int kc = kb + t4;
                af[mt][0] = As[rm * SA + kc];
                af[mt][1] = As[(rm + 8) * SA + kc];
                af[mt][2] = As[rm * SA + kc + 4];
                af[mt][3] = As[(rm + 8) * SA + kc + 4];
            }
#pragma unroll
            for (int nt = 0; nt < 8; nt++) {
                const int cn = n_woff + nt * 8 + g4;
                uint32_t bf[2] = { Bs[cn * SB + kb + t4], Bs[cn * SB + kb + t4 + 4] };
#pragma unroll
                for (int mt = 0; mt < 2; mt++) mma_tf32(acc[mt][nt], af[mt], bf);
            }
        }
        __syncthreads();
    }

    // softmax (scale 0.125 folded)
    float lmax[2][2] = { {-1e30f, -1e30f}, {-1e30f, -1e30f} };
#pragma unroll
    for (int mt = 0; mt < 2; mt++)
#pragma unroll
        for (int nt = 0; nt < 8; nt++)
#pragma unroll
            for (int q = 0; q < 4; q++) {
                acc[mt][nt][q] *= 0.125f;
                lmax[mt][q >> 1] = fmaxf(lmax[mt][q >> 1], acc[mt][nt][q]);
            }
#pragma unroll
    for (int o = 1; o <= 2; o <<= 1)
#pragma unroll
        for (int mt = 0; mt < 2; mt++)
#pragma unroll
            for (int hh = 0; hh < 2; hh++)
                lmax[mt][hh] = fmaxf(lmax[mt][hh], __shfl_xor_sync(0xffffffffu, lmax[mt][hh], o));
    if (t4 == 0)
#pragma unroll
        for (int mt = 0; mt < 2; mt++)
#pragma unroll
            for (int hh = 0; hh < 2; hh++)
                red[(m_woff + mt * 16 + hh * 8 + g4) * 4 + wn] = lmax[mt][hh];
    __syncthreads();
    float rmax[2][2];
#pragma unroll
    for (int mt = 0; mt < 2; mt++)
#pragma unroll
        for (int hh = 0; hh < 2; hh++) {
            const int rb = (m_woff + mt * 16 + hh * 8 + g4) * 4;
            rmax[mt][hh] = fmaxf(fmaxf(red[rb], red[rb + 1]), fmaxf(red[rb + 2], red[rb + 3]));
        }
    __syncthreads();
    float lsum[2][2] = { {0.f, 0.f}, {0.f, 0.f} };
#pragma unroll
    for (int mt = 0; mt < 2; mt++)
#pragma unroll
        for (int nt = 0; nt < 8; nt++)
#pragma unroll
            for (int q = 0; q < 4; q++) {
                const float e = expf(acc[mt][nt][q] - rmax[mt][q >> 1]);
                acc[mt][nt][q] = e;
                lsum[mt][q >> 1] += e;
            }
#pragma unroll
    for (int o = 1; o <= 2; o <<= 1)
#pragma unroll
        for (int mt = 0; mt < 2; mt++)
#pragma unroll
            for (int hh = 0; hh < 2; hh++)
                lsum[mt][hh] += __shfl_xor_sync(0xffffffffu, lsum[mt][hh], o);
    if (t4 == 0)
#pragma unroll
        for (int mt = 0; mt < 2; mt++)
#pragma unroll
            for (int hh = 0; hh < 2; hh++)
                red[(m_woff + mt * 16 + hh * 8 + g4) * 4 + wn] = lsum[mt][hh];
    __syncthreads();
#pragma unroll
    for (int mt = 0; mt < 2; mt++) {
        float ri[2];
#pragma unroll
        for (int hh = 0; hh < 2; hh++) {
            const int rb = (m_woff + mt * 16 + hh * 8 + g4) * 4;
            ri[hh] = 1.0f / (red[rb] + red[rb + 1] + red[rb + 2] + red[rb + 3]);
        }
#pragma unroll
        for (int nt = 0; nt < 8; nt++) {
            acc[mt][nt][0] *= ri[0]; acc[mt][nt][1] *= ri[0];
            acc[mt][nt][2] *= ri[1]; acc[mt][nt][3] *= ri[1];
        }
    }

    // phase 2: O = P @ za3v in 4 chunks of K=64
    const float* Zb = za3v + (long)bh * LM * DH;
    float accO[2][2][4];
#pragma unroll
    for (int mt = 0; mt < 2; mt++)
#pragma unroll
        for (int nt = 0; nt < 2; nt++)
#pragma unroll
            for (int q = 0; q < 4; q++) accO[mt][nt][q] = 0.f;

    for (int c = 0; c < 4; c++) {
        __syncthreads();   // previous MMA done (and phase-1 smem free at c=0)
        if (wn == c) {
#pragma unroll
            for (int mt = 0; mt < 2; mt++) {
                const int r = m_woff + mt * 16 + g4;
#pragma unroll
                for (int nt = 0; nt < 8; nt++) {
                    const int lc = nt * 8 + 2 * t4;
                    Ps[r * 68 + lc]           = f2tf(acc[mt][nt][0]);
                    Ps[r * 68 + lc + 1]       = f2tf(acc[mt][nt][1]);
                    Ps[(r + 8) * 68 + lc]     = f2tf(acc[mt][nt][2]);
                    Ps[(r + 8) * 68 + lc + 1] = f2tf(acc[mt][nt][3]);
                }
            }
        }
        // load za3v chunk rows [64c, 64c+64)
#pragma unroll
        for (int i = 0; i < 2; i++) {
            const int idx = tid + i * 512;
            const int zr = idx >> 4, zc = (idx & 15) << 2;
            const float4 v = *reinterpret_cast<const float4*>(Zb + (long)(c * 64 + zr) * DH + zc);
            uint4 t = { f2tf(v.x), f2tf(v.y), f2tf(v.z), f2tf(v.w) };
            *reinterpret_cast<uint4*>(&Zs[zr * 72 + zc]) = t;
        }
        __syncthreads();
#pragma unroll
        for (int kb = 0; kb < 64; kb += 8) {
            uint32_t af[2][4];
#pragma unroll
            for (int mt = 0; mt < 2; mt++) {
                const int rm = m_woff + mt * 16 + g4;
                af[mt][0] = Ps[rm * 68 + kb + t4];
                af[mt][1] = Ps[(rm + 8) * 68 + kb + t4];
                af[mt][2] = Ps[rm * 68 + kb + t4 + 4];
                af[mt][3] = Ps[(rm + 8) * 68 + kb + t4 + 4];
            }
#pragma unroll
            for (int nt = 0; nt < 2; nt++) {
                const int cn = wn * 16 + nt * 8 + g4;
                uint32_t bf[2] = { Zs[(kb + t4) * 72 + cn], Zs[(kb + t4 + 4) * 72 + cn] };
#pragma unroll
                for (int mt = 0; mt < 2; mt++) mma_tf32(accO[mt][nt], af[mt], bf);
            }
        }
    }

    // epilogue: + conv res, write ctx in (b, n, h*dh) layout
    const float* rbase = res + (long)bh * SEQ * DH;
    float* cbase = ctx + (long)zb * SEQ * DIM + zh * DH;
#pragma unroll
    for (int mt = 0; mt < 2; mt++) {
        const int r = row0 + m_woff + mt * 16 + g4;
#pragma unroll
        for (int nt = 0; nt < 2; nt++) {
            const int cc = wn * 16 + nt * 8 + 2 * t4;
            const float2 r0 = *reinterpret_cast<const float2*>(rbase + (long)r * DH + cc);
            const float2 r1 = *reinterpret_cast<const float2*>(rbase + (long)(r + 8) * DH + cc);
            *reinterpret_cast<float2*>(cbase + (long)r * DIM + cc) =
                make_float2(accO[mt][nt][0] + r0.x, accO[mt][nt][1] + r0.y);
            *reinterpret_cast<float2*>(cbase + (long)(r + 8) * DIM + cc) =
                make_float2(accO[mt][nt][2] + r1.x, accO[mt][nt][3] + r1.y);
        }
    }
}

// ---------------- flash-style fused a3v = softmax(q_l @ k^T) @ v -----------------
// Grid (LM/128, BH), 512 threads. Online softmax over SEQ in tiles of 128.
constexpr int FL_SMEM_WORDS = 8704 + 8704 + 9216 + 16896 + 512;  // 44032 (176KB)

__global__ __launch_bounds__(512, 1)
void flash_a3v(const float* __restrict__ ql, const float* __restrict__ qkv,
               float* __restrict__ a3v)
{
    extern __shared__ uint32_t dsm[];
    uint32_t* Qs = dsm;                       // [128][68]
    uint32_t* Ks = Qs + 8704;                 // [128][68]
    uint32_t* Vs = Ks + 8704;                 // [128][72]
    uint32_t* Ps = Vs + 9216;                 // [128][132]
    float*    red = (float*)(Ps + 16896);     // [128][4]

    const int bh = blockIdx.y;
    const int b = bh >> 3, h = bh & 7;
    const int row0 = blockIdx.x * 128;
    const int tid = threadIdx.x, lane = tid & 31, warp = tid >> 5;
    const int wm = warp >> 2, wn = warp & 3;
    const int g4 = lane >> 2, t4 = lane & 3;
    const int m_woff = wm * 32;

    const float* kbase = qkv + DIM     + (long)b * SEQ * QKVW + h * DH;
    const float* vbase = qkv + 2 * DIM + (long)b * SEQ * QKVW + h * DH;
    const float* qbase = ql + (long)bh * LM * DH + (long)row0 * DH;

    // load Q tile (128 x 64)
#pragma unroll
    for (int i = 0; i < 4; i++) {
        const int idx = tid + i * 512;
        const int r = idx >> 4, c = (idx & 15) << 2;
        const float4 v = *reinterpret_cast<const float4*>(qbase + (long)r * DH + c);
        uint4 t = { f2tf(v.x), f2tf(v.y), f2tf(v.z), f2tf(v.w) };
        *reinterpret_cast<uint4*>(&Qs[r * 68 + c]) = t;
    }

    float accO[2][2][4];
#pragma unroll
    for (int mt = 0; mt < 2; mt++)
#pragma unroll
        for (int nt = 0; nt < 2; nt++)
#pragma unroll
            for (int q = 0; q < 4; q++) accO[mt][nt][q] = 0.f;
    float mrow[2][2] = { {-1e30f, -1e30f}, {-1e30f, -1e30f} };
    float srow[2][2] = { {0.f, 0.f}, {0.f, 0.f} };

    for (int kb0 = 0; kb0 < SEQ; kb0 += 128) {
        __syncthreads();
#pragma unroll
        for (int i = 0; i < 4; i++) {
            const int idx = tid + i * 512;
            const int r = idx >> 4, c = (idx & 15) << 2;
            const float4 kv = *reinterpret_cast<const float4*>(kbase + (long)(kb0 + r) * QKVW + c);
            uint4 tk = { f2tf(kv.x), f2tf(kv.y), f2tf(kv.z), f2tf(kv.w) };
            *reinterpret_cast<uint4*>(&Ks[r * 68 + c]) = tk;
            const float4 vv = *reinterpret_cast<const float4*>(vbase + (long)(kb0 + r) * QKVW + c);
            uint4 tv = { f2tf(vv.x), f2tf(vv.y), f2tf(vv.z), f2tf(vv.w) };
            *reinterpret_cast<uint4*>(&Vs[r * 72 + c]) = tv;
        }
        __syncthreads();

        // S = Q @ Ktile^T : 128x128, K=64
        float accS[2][4][4];
#pragma unroll
        for (int mt = 0; mt < 2; mt++)
#pragma unroll
            for (int nt = 0; nt < 4; nt++)
#pragma unroll
                for (int q = 0; q < 4; q++) accS[mt][nt][q] = 0.f;
#pragma unroll
        for (int kb = 0; kb < 64; kb += 8) {
            uint32_t af[2][4];
#pragma unroll
            for (int mt = 0; mt < 2; mt++) {
                const int rm = m_woff + mt * 16 + g4;
                af[mt][0] = Qs[rm * 68 + kb + t4];
                af[mt][1] = Qs[(rm + 8) * 68 + kb + t4];
                af[mt][2] = Qs[rm * 68 + kb + t4 + 4];
                af[mt][3] = Qs[(rm + 8) * 68 + kb + t4 + 4];
            }
#pragma unroll
            for (int nt = 0; nt < 4; nt++) {
                const int cn = wn * 32 + nt * 8 + g4;
                uint32_t bf[2] = { Ks[cn * 68 + kb + t4], Ks[cn * 68 + kb + t4 + 4] };
#pragma unroll
                for (int mt = 0; mt < 2; mt++) mma_tf32(accS[mt][nt], af[mt], bf);
            }
        }

        float cmax[2][2] = { {-1e30f, -1e30f}, {-1e30f, -1e30f} };
#pragma unroll
        for (int mt = 0; mt < 2; mt++)
#pragma unroll
            for (int nt = 0; nt < 4; nt++)
#pragma unroll
                for (int q = 0; q < 4; q++)
                    cmax[mt][q >> 1] = fmaxf(cmax[mt][q >> 1], accS[mt][nt][q]);
#pragma unroll
        for (int o = 1; o <= 2; o <<= 1)
#pragma unroll
            for (int mt = 0; mt < 2; mt++)
#pragma unroll
                for (int hh = 0; hh < 2; hh++)
                    cmax[mt][hh] = fmaxf(cmax[mt][hh], __shfl_xor_sync(0xffffffffu, cmax[mt][hh], o));
        if (t4 == 0)
#pragma unroll
            for (int mt = 0; mt < 2; mt++)
#pragma unroll
                for (int hh = 0; hh < 2; hh++)
                    red[(m_woff + mt * 16 + hh * 8 + g4) * 4 + wn] = cmax[mt][hh];
        __syncthreads();
        float cscale[2][2], mnew[2][2];
#pragma unroll
        for (int mt = 0; mt < 2; mt++)
#pragma unroll
            for (int hh = 0; hh < 2; hh++) {
                const int rb = (m_woff + mt * 16 + hh * 8 + g4) * 4;
                const float cm = fmaxf(fmaxf(red[rb], red[rb + 1]), fmaxf(red[rb + 2], red[rb + 3]));
                mnew[mt][hh] = fmaxf(mrow[mt][hh], cm);
                cscale[mt][hh] = expf(mrow[mt][hh] - mnew[mt][hh]);
                mrow[mt][hh] = mnew[mt][hh];
            }
        __syncthreads();

        float lsum[2][2] = { {0.f, 0.f}, {0.f, 0.f} };
#pragma unroll
        for (int mt = 0; mt < 2; mt++)
#pragma unroll
            for (int nt = 0; nt < 4; nt++)
#pragma unroll
                for (int q = 0; q < 4; q++) {
                    const float e = expf(accS[mt][nt][q] - mnew[mt][q >> 1]);
                    accS[mt][nt][q] = e;
                    lsum[mt][q >> 1] += e;
                }
#pragma unroll
        for (int o = 1; o <= 2; o <<= 1)
#pragma unroll
            for (int mt = 0; mt < 2; mt++)
#pragma unroll
                for (int hh = 0; hh < 2; hh++)
                    lsum[mt][hh] += __shfl_xor_sync(0xffffffffu, lsum[mt][hh], o);
        if (t4 == 0)
#pragma unroll
            for (int mt = 0; mt < 2; mt++)
#pragma unroll
                for (int hh = 0; hh < 2; hh++)
                    red[(m_woff + mt * 16 + hh * 8 + g4) * 4 + wn] = lsum[mt][hh];
        __syncthreads();
#pragma unroll
        for (int mt = 0; mt < 2; mt++)
#pragma unroll
            for (int hh = 0; hh < 2; hh++) {
                const int rb = (m_woff + mt * 16 + hh * 8 + g4) * 4;
                const float cs = red[rb] + red[rb + 1] + red[rb + 2] + red[rb + 3];
                srow[mt][hh] = srow[mt][hh] * cscale[mt][hh] + cs;
            }
#pragma unroll
        for (int mt = 0; mt < 2; mt++)
#pragma unroll
            for (int nt = 0; nt < 2; nt++)
#pragma unroll
                for (int q = 0; q < 4; q++) accO[mt][nt][q] *= cscale[mt][q >> 1];

#pragma unroll
        for (int mt = 0; mt < 2; mt++) {
            const int r = m_woff + mt * 16 + g4;
#pragma unroll
            for (int nt = 0; nt < 4; nt++) {
                const int cb = wn * 32 + nt * 8 + 2 * t4;
                Ps[r * 132 + cb]           = f2tf(accS[mt][nt][0]);
                Ps[r * 132 + cb + 1]       = f2tf(accS[mt][nt][1]);
                Ps[(r + 8) * 132 + cb]     = f2tf(accS[mt][nt][2]);
                Ps[(r + 8) * 132 + cb + 1] = f2tf(accS[mt][nt][3]);
            }
        }
        __syncthreads();

        // O += P @ Vtile : 128x64, K=128
#pragma unroll
        for (int kb = 0; kb < 128; kb += 8) {
            uint32_t af[2][4];
#pragma unroll
            for (int mt = 0; mt < 2; mt++) {
                const int rm = m_woff + mt * 16 + g4;
                af[mt][0] = Ps[rm * 132 + kb + t4];
                af[mt][1] = Ps[(rm + 8) * 132 + kb + t4];
                af[mt][2] = Ps[rm * 132 + kb + t4 + 4];
                af[mt][3] = Ps[(rm + 8) * 132 + kb + t4 + 4];
            }
#pragma unroll
            for (int nt = 0; nt < 2; nt++) {
                const int cn = wn * 16 + nt * 8 + g4;
                uint32_t bf[2] = { Vs[(kb + t4) * 72 + cn], Vs[(kb + t4 + 4) * 72 + cn] };
#pragma unroll
                for (int mt = 0; mt < 2; mt++) mma_tf32(accO[mt][nt], af[mt], bf);
            }
        }
    }

    float* obase = a3v + (long)bh * LM * DH;
#pragma unroll
    for (int mt = 0; mt < 2; mt++) {
        const int r = row0 + m_woff + mt * 16 + g4;
        const float i0 = 1.0f / srow[mt][0];
        const float i1 = 1.0f / srow[mt][1];
#pragma unroll
        for (int nt = 0; nt < 2; nt++) {
            const int c = wn * 16 + nt * 8 + 2 * t4;
            *reinterpret_cast<float2*>(obase + (long)r * DH + c) =
                make_float2(accO[mt][nt][0] * i0, accO[mt][nt][1] * i0);
            *reinterpret_cast<float2*>(obase + (long)(r + 8) * DH + c) =
                make_float2(accO[mt][nt][2] * i1, accO[mt][nt][3] * i1);
        }
    }
}

// ---------------- LayerNorm ----------------
__global__ void ln_kernel(const float* __restrict__ x, const float* __restrict__ gamma,
                          const float* __restrict__ beta, float* __restrict__ xn)
{
    const int t = blockIdx.x;
    const int tid = threadIdx.x;
    const float2 v = reinterpret_cast<const float2*>(x + (long)t * DIM)[tid];
    float s  = v.x + v.y;
    float ss = v.x * v.x + v.y * v.y;
#pragma unroll
    for (int o = 16; o; o >>= 1) {
        s  += __shfl_xor_sync(0xffffffffu, s,  o);
        ss += __shfl_xor_sync(0xffffffffu, ss, o);
    }
    __shared__ float sms[8], smss[8];
    __shared__ float mu_s, rs_s;
    if ((tid & 31) == 0) { sms[tid >> 5] = s; smss[tid >> 5] = ss; }
    __syncthreads();
    if (tid == 0) {
        float S = 0.f, SS = 0.f;
        for (int i = 0; i < 8; i++) { S += sms[i]; SS += smss[i]; }
        const float mu = S / DIM;
        mu_s = mu;
        rs_s = rsqrtf(SS / DIM - mu * mu + 1e-5f);
    }
    __syncthreads();
    const float mu = mu_s, rs = rs_s;
    const float2 g  = reinterpret_cast<const float2*>(gamma)[tid];
    const float2 be = reinterpret_cast<const float2*>(beta)[tid];
    float2 o;
    o.x = (v.x - mu) * rs * g.x + be.x;
    o.y = (v.y - mu) * rs * g.y + be.y;
    reinterpret_cast<float2*>(xn + (long)t * DIM)[tid] = o;
}

// ---------------- landmark means (q already scaled by dh^-0.5) ----------------
__global__ void landmark_kernel(const float* __restrict__ qkv,
                                float* __restrict__ ql, float* __restrict__ kl)
{
    const int idx = blockIdx.x * blockDim.x + threadIdx.x;
    if (idx >= BH * LM * DH) return;
    const int d  = idx % DH;
    const int j  = (idx / DH) % LM;
    const int bh = idx / (DH * LM);
    const int b = bh / H, h = bh % H;
    const float* base = qkv + ((long)(b * SEQ + j * LSZ)) * QKVW + h * DH + d;
    float sq = 0.f, sk = 0.f;
#pragma unroll
    for (int l = 0; l < LSZ; l++) {
        sq += base[(long)l * QKVW];
        sk += base[(long)l * QKVW + DIM];
    }
    ql[idx] = sq * (1.0f / LSZ) * 0.125f;
    kl[idx] = sk * (1.0f / LSZ);
}

// ---------------- pinv helpers ----------------
__global__ void init_norms() { g_rowmax_i = 0; g_colmax_i = 0; }

__global__ void pinv_norms(const float* __restrict__ a2)
{
    const int bh = blockIdx.x, tid = threadIdx.x;
    const float* X = a2 + (long)bh * LM * LM;
    float rs = 0.f, cs = 0.f;
    for (int j = 0; j < LM; j++) {
        rs += fabsf(X[(long)tid * LM + j]);
        cs += fabsf(X[(long)j * LM + tid]);
    }
    __shared__ float sm[256];
    sm[tid] = rs; __syncthreads();
    for (int o = 128; o; o >>= 1) { if (tid < o) sm[tid] = fmaxf(sm[tid], sm[tid + o]); __syncthreads(); }
    if (tid == 0) atomicMax(&g_rowmax_i, __float_as_int(sm[0]));
    __syncthreads();
    sm[tid] = cs; __syncthreads();
    for (int o = 128; o; o >>= 1) { if (tid < o) sm[tid] = fmaxf(sm[tid], sm[tid + o]); __syncthreads(); }
    if (tid == 0) atomicMax(&g_colmax_i, __float_as_int(sm[0]));
}

__global__ void pinv_z0(const float* __restrict__ a2, float* __restrict__ z)
{
    const long idx = (long)blockIdx.x * blockDim.x + threadIdx.x;
    if (idx >= (long)BH * LM * LM) return;
    const float inv = 1.0f / (__int_as_float(g_rowmax_i) * __int_as_float(g_colmax_i));
    const int j  = (int)(idx % LM);
    const int i  = (int)((idx / LM) % LM);
    const int bh = (int)(idx / ((long)LM * LM));
    z[idx] = a2[(long)bh * LM * LM + (long)j * LM + i] * inv;
}

// ---------------- depthwise conv over sequence (kernel 33) ----------------
__global__ void conv_kernel(const float* __restrict__ qkv, const float* __restrict__ w,
                            float* __restrict__ res)
{
    const int bh = blockIdx.y;
    const int b = bh / H, h = bh % H;
    const int i0 = blockIdx.x * 64;
    __shared__ float sm[96][DH];
    __shared__ float wsh[CK];
    const int tid = threadIdx.x;
    if (tid < CK) wsh[tid] = w[h * CK + tid];
    const float* vbase = qkv + 2 * DIM + h * DH + (long)b * SEQ * QKVW;
    for (int e = tid; e < 96 * DH; e += 256) {
        const int r = e / DH, d = e % DH;
        const int gi = i0 + r - 16;
        sm[r][d] = (gi >= 0 && gi < SEQ) ? vbase[(long)gi * QKVW + d] : 0.0f;
    }
    __syncthreads();
    float* rbase = res + (long)bh * SEQ * DH + (long)i0 * DH;
    for (int e = tid; e < 64 * DH; e += 256) {
        const int il = e / DH, d = e % DH;
        float s = 0.f;
#pragma unroll
        for (int t = 0; t < CK; t++) s = fmaf(sm[il + t][d], wsh[t], s);
        rbase[e] = s;
    }
}

// ---------------- host orchestration ----------------
extern "C" void kernel_launch(void* const* d_in, const int* in_sizes, int n_in,
                              void* d_out, int out_size)
{
    const float* x     = (const float*)d_in[0];
    const float* gamma = (const float*)d_in[1];
    const float* beta  = (const float*)d_in[2];
    const float* Wqkv  = (const float*)d_in[3];
    const float* Wout  = (const float*)d_in[4];
    const float* bout  = (const float*)d_in[5];
    const float* convw = (const float*)d_in[6];
    float* out = (float*)d_out;

    float *p_xn, *p_qkv, *p_ql, *p_kl, *p_a2, *p_z, *p_z2,
          *p_xz, *p_t, *p_w, *p_a3v, *p_za3v, *p_res, *p_ctx;
    cudaGetSymbolAddress((void**)&p_xn,   g_xn);
    cudaGetSymbolAddress((void**)&p_qkv,  g_qkv);
    cudaGetSymbolAddress((void**)&p_ql,   g_ql);
    cudaGetSymbolAddress((void**)&p_kl,   g_kl);
    cudaGetSymbolAddress((void**)&p_a2,   g_a2);
    cudaGetSymbolAddress((void**)&p_z,    g_z);
    cudaGetSymbolAddress((void**)&p_z2,   g_z2);
    cudaGetSymbolAddress((void**)&p_xz,   g_xz);
    cudaGetSymbolAddress((void**)&p_t,    g_t);
    cudaGetSymbolAddress((void**)&p_w,    g_w);
    cudaGetSymbolAddress((void**)&p_a3v,  g_a3v);
    cudaGetSymbolAddress((void**)&p_za3v, g_za3v);
    cudaGetSymbolAddress((void**)&p_res,  g_res);
    cudaGetSymbolAddress((void**)&p_ctx,  g_ctx);

    static bool attr_set = false;
    if (!attr_set) {
        cudaFuncSetAttribute(flash_a3v, cudaFuncAttributeMaxDynamicSharedMemorySize,
                             FL_SMEM_WORDS * 4);
        cudaFuncSetAttribute(fused_a1ctx, cudaFuncAttributeMaxDynamicSharedMemorySize,
                             FA_SMEM_WORDS * 4);
        attr_set = true;
    }

    const long sLD_b = (long)H * LM * DH, sLD_h = (long)LM * DH;
    const long sMM_b = (long)H * LM * LM,  sMM_h = (long)LM * LM;

    // 1) LayerNorm
    ln_kernel<<<TOK, 256>>>(x, gamma, beta, p_xn);

    // 2) QKV projection
    tgemm<128,128,16,2,4,false><<<dim3(QKVW/128, TOK/128, 1), 256>>>(
        p_xn, Wqkv, p_qkv, DIM, QKVW, QKVW, DIM,
        0,0, 0,0, 0,0, 1.0f, nullptr, nullptr, 0.f, 0, 0,0);

    // 3) landmarks
    landmark_kernel<<<(BH*LM*DH)/256, 256>>>(p_qkv, p_ql, p_kl);

    // 4) a2 = softmax(ql @ kl^T) — fused softmax epilogue
    tgemm_sm<<<dim3(1, LM/128, BH), 512>>>(p_ql, DH, sLD_h, p_kl, p_a2, sMM_h, 1.0f);

    // 5) a3v = softmax(q_l @ k^T) @ v — flash-fused
    flash_a3v<<<dim3(LM/128, BH), 512, FL_SMEM_WORDS * 4>>>(p_ql, p_qkv, p_a3v);

    // 6) pinv(a2) via Newton-Schulz (elementwise folded into epilogues)
    init_norms<<<1,1>>>();
    pinv_norms<<<BH, 256>>>(p_a2);
    pinv_z0<<<(BH*LM*LM)/256, 256>>>(p_a2, p_z);
    for (int it = 0; it < 6; it++) {
        float* zin  = (it & 1) ? p_z2 : p_z;
        float* zout = (it & 1) ? p_z  : p_z2;
        tgemm<128,128,16,2,4,false><<<dim3(2,2,BH), 256>>>(
            p_a2, zin, p_xz, LM, LM, LM, LM,
            sMM_b, sMM_h, sMM_b, sMM_h, sMM_b, sMM_h, 1.0f, nullptr, nullptr, 0.f, 0, 0,0);
        tgemm<128,128,16,2,4,false><<<dim3(2,2,BH), 256>>>(
            p_xz, p_xz, p_w, LM, LM, LM, LM,
            sMM_b, sMM_h, sMM_b, sMM_h, sMM_b, sMM_h, -1.0f, nullptr, p_xz, 7.0f, LM, sMM_b, sMM_h);
        tgemm<128,128,16,2,4,false><<<dim3(2,2,BH), 256>>>(
            p_xz, p_w, p_t, LM, LM, LM, LM,
            sMM_b, sMM_h, sMM_b, sMM_h, sMM_b, sMM_h, -1.0f, nullptr, p_xz, 15.0f, LM, sMM_b, sMM_h);
        tgemm<128,128,16,2,4,false><<<dim3(2,2,BH), 256>>>(
            zin, p_t, zout, LM, LM, LM, LM,
            sMM_b, sMM_h, sMM_b, sMM_h, sMM_b, sMM_h, -0.25f, nullptr, zin, 3.25f, LM, sMM_b, sMM_h);
    }

    // 7) za3v = z @ a3v
    tgemm<128,64,16,4,2,false><<<dim3(1, LM/128, BH), 256>>>(
        p_z, p_a3v, p_za3v, LM, DH, DH, LM,
        sMM_b, sMM_h, sLD_b, sLD_h, sLD_b, sLD_h, 1.0f, nullptr, nullptr, 0.f, 0, 0,0);

    // 8) depthwise conv residual over v
    conv_kernel<<<dim3(SEQ/64, BH), 256>>>(p_qkv, convw, p_res);

    // 9) ctx = softmax(0.125 q@kl^T) @ za3v + conv_res  (a1 never materialized)
    fused_a1ctx<<<dim3(SEQ/128, BH), 512, FA_SMEM_WORDS * 4>>>(
        p_qkv, p_kl, p_za3v, p_res, p_ctx);

    // 10) final: out = ctx @ W_out + b_out + x
    tgemm<128,128,16,2,4,false><<<dim3(DIM/128, TOK/128, 1), 256>>>(
        p_ctx, Wout, out, DIM, DIM, DIM, DIM,
        0,0, 0,0, 0,0, 1.0f, bout, x, 1.0f, DIM, 0,0);
}